// round 14
// baseline (speedup 1.0000x reference)
#include <cuda_runtime.h>
#include <cstdint>

#define LSEQ 256
#define NB   8
#define NC   64
#define PTOT 37120   // padded row-layout size (rs(255) = 36607)
#define DPAD 512     // slack for discarded-lane bulk reads
#define WB   8       // widths per pass

// t = max_c scores, padded-row layout: g_td[b*PTOT + rs(i) + (e-i-1)]
__device__ float g_td[NB * PTOT];

// Bank-aligned row starts, closed form: rs(i) % 32 == i % 32.
__host__ __device__ __forceinline__ int rs_pad(int i) {
    const int q = i >> 5, k = i & 31;
    const int g = (k <= 30) ? ((k * (k + 3)) >> 1) : 495;
    return i * 255 - ((i * (i - 1)) >> 1) + 496 * q + g;
}

__device__ __forceinline__ uint32_t smem_u32(const void* p) {
    uint32_t a;
    asm("{ .reg .u64 t; cvta.to.shared.u64 t, %1; cvt.u32.u64 %0, t; }"
        : "=r"(a) : "l"(p));
    return a;
}

// ---------------------------------------------------------------------------
// Kernel 1: t[b,i,e] = max over C of scores[b,i,e,:], upper triangle only.
// ---------------------------------------------------------------------------
__global__ void max_kernel(const float* __restrict__ scores) {
    const int i    = blockIdx.x;          // 0 .. 254
    const int b    = blockIdx.y;
    const int warp = threadIdx.x >> 5;
    const int lane = threadIdx.x & 31;
    const int base = b * PTOT + rs_pad(i) - i - 1;

    for (int e = i + 1 + warp; e < LSEQ; e += 8) {
        const float* p = scores + (((size_t)b * LSEQ + i) * LSEQ + e) * NC;
        float v = fmaxf(p[lane], p[lane + 32]);
        #pragma unroll
        for (int o = 16; o > 0; o >>= 1)
            v = fmaxf(v, __shfl_xor_sync(0xffffffffu, v, o));
        if (lane == 0)
            g_td[base + e] = v;
    }
}

// ---------------------------------------------------------------------------
// Kernel 2: CKY inside, 2-CTA cluster per batch, 8 widths per pass.
//  Bulk: j in [8, w-1] legal for all 8 widths (both children old); the 8
//    right operands are adjacent (immediate offsets). j-range split across
//    the 2 CTAs and the per-CTA groups.
//  Pre-combine: 1024 threads cover 8x256 (2 slots each), push to peer
//    mailbox (double-buffered) + one cluster barrier.
//  Serial tail (tid<256, 8 sub-steps, partial barriers): low fixups j in
//    [1, min(7, wd-1)], high fixups j in [w, wd-1]; sequential width order
//    makes every referenced diagonal available.
// ---------------------------------------------------------------------------
__global__ __launch_bounds__(1024, 1) __cluster_dims__(2, 1, 1)
void dp_kernel(const int* __restrict__ lens, float* __restrict__ out) {
    const int b = blockIdx.y;
    extern __shared__ float S[];
    float* D    = S;                              // PTOT + DPAD chart
    float* P0   = S + PTOT + DPAD;                // 8 x 1024 bulk partials
    float* VV   = P0 + 8 * 1024;                  // 8 x 256 local pre-combined
    float* MAIL = VV + 2048;                      // 2 x (8 x 256) peer mailbox
    int*   rs   = (int*)(MAIL + 4096);            // padded row starts
    const float* tb  = g_td + b * PTOT;
    const int    tid = threadIdx.x;

    uint32_t rank;
    asm("mov.u32 %0, %%cluster_ctarank;" : "=r"(rank));

    // Peer mailbox base for this thread's 2 slots (parity adds 8KB).
    uint32_t mail_rem;
    {
        uint32_t loc = smem_u32(S)
                     + (uint32_t)(PTOT + DPAD + 8192 + 2048 + tid) * 4u;
        asm("mapa.shared::cluster.u32 %0, %1, %2;"
            : "=r"(mail_rem) : "r"(loc), "r"(rank ^ 1u));
    }

    if (tid < 256) rs[tid] = rs_pad(tid);
    __syncthreads();
    if (tid < 255) D[rs[tid]] = tb[rs[tid]];      // width-1 diagonal
    __syncthreads();

    // Serial-thread state: cached row start + prefetched t for widths 2..9.
    int   rsc = 0, lim = 0;
    float tt[WB];
    if (tid < 256) {
        rsc = rs[tid];
        lim = rsc + (tid < 254 ? 254 - tid : 0);
        #pragma unroll
        for (int q = 0; q < WB; ++q) {
            int idx = rsc + 1 + q;
            tt[q] = tb[idx < lim ? idx : lim];
        }
    }
    __syncthreads();

    int par = 0;
    for (int w = 2; w < LSEQ; w += WB) {
        const int n  = LSEQ - w;             // cells at base width w
        const int sB = (n > 128) ? 8 : (n > 64 ? 7 : 6);
        const int c  = tid & ((1 << sB) - 1);
        const int gg = ((int)rank << (10 - sB)) + (tid >> sB);  // global group

        // ---- bulk: j in [8, w-1] for all eight widths (half range per CTA)
        float acc[WB];
        #pragma unroll
        for (int d = 0; d < WB; ++d) acc[d] = -1e30f;
        if (c < n && w > WB) {
            const int m   = w - WB;
            const int jlo = WB + ((gg * m) >> (11 - sB));
            const int jhi = WB + (((gg + 1) * m) >> (11 - sB));
            if (jlo < jhi) {
                const int lb = rs[c] - 1;        // left: D[lb + j]
                int tp = c + jlo;                // rs-table index
                int rb = w - jlo - 1;            // right col (base width)
                #pragma unroll 2
                for (int j = jlo; j < jhi; ++j) {
                    const float L  = D[lb + j];
                    const int   ra = rs[tp] + rb;
                    #pragma unroll
                    for (int d = 0; d < WB; ++d)
                        acc[d] = fmaxf(acc[d], L + D[ra + d]);
                    ++tp; --rb;
                }
            }
        }
        #pragma unroll
        for (int d = 0; d < WB; ++d) P0[(d << 10) + tid] = acc[d];
        __syncthreads();

        // ---- pre-combine (2 slots per thread) + push to peer mailbox
        {
            const int G = 1024 >> sB;
            #pragma unroll
            for (int h = 0; h < 2; ++h) {
                const int slot = tid + (h << 10);      // (d<<8)+cc, d=0..7
                const int d    = slot >> 8;
                const int cc   = slot & 255;
                const float* PP = P0 + (d << 10);
                float v = -1e30f;
                if (cc < n) {
                    #pragma unroll 4
                    for (int k = 0; k < G; ++k)
                        v = fmaxf(v, PP[(k << sB) + cc]);
                }
                VV[slot] = v;
                asm volatile("st.shared::cluster.b32 [%0], %1;"
                             :: "r"(mail_rem + (uint32_t)(h << 12)
                                             + (par ? 8192u : 0u)),
                                "r"(__float_as_uint(v)) : "memory");
            }
        }
        asm volatile("barrier.cluster.arrive.aligned;" ::: "memory");
        asm volatile("barrier.cluster.wait.aligned;"   ::: "memory");

        // ---- serial tail: merge + ordered fixups + store, width by width
        if (tid < 256) {
            const float* MB = MAIL + (par << 11);
            #pragma unroll
            for (int d = 0; d < WB; ++d) {
                const int wd = w + d;
                if (wd <= 255 && tid < LSEQ - wd) {
                    float v = fmaxf(VV[(d << 8) + tid], MB[(d << 8) + tid]);
                    // low fixups: j in [1, min(7, wd-1)]
                    #pragma unroll
                    for (int j = 1; j <= 7; ++j)
                        if (j < wd && j < w + d)   // j <= wd-1 (j==wd skip)
                            v = fmaxf(v, D[rsc + j - 1] +
                                         D[rs[tid + j] + wd - j - 1]);
                    // high fixups: j in [max(w,8), wd-1]
                    for (int j = (w > WB ? w : WB); j < wd; ++j)
                        v = fmaxf(v, D[rsc + j - 1] +
                                     D[rs[tid + j] + wd - j - 1]);
                    D[rsc + wd - 1] = v + tt[d];
                }
                asm volatile("bar.sync 1, 256;" ::: "memory");
            }
            // prefetch t for next pass (widths w+8..w+15), clamped
            #pragma unroll
            for (int q = 0; q < WB; ++q) {
                int idx = rsc + w + WB - 1 + q;
                tt[q] = tb[idx < lim ? idx : lim];
            }
        }
        par ^= 1;
        __syncthreads();
    }

    if (rank == 0 && tid == 0) {
        int len = lens[b];
        len = len < 1 ? 1 : (len > 255 ? 255 : len);
        out[b] = D[len - 1];                 // s[0, len] = row 0, col len-1
    }
}

// ---------------------------------------------------------------------------
extern "C" void kernel_launch(void* const* d_in, const int* in_sizes, int n_in,
                              void* d_out, int out_size) {
    const float* scores = (const float*)d_in[0];
    const int*   lens   = (const int*)d_in[1];
    float*       out    = (float*)d_out;
    (void)in_sizes; (void)n_in; (void)out_size;

    const int smem = (PTOT + DPAD + 8 * 1024 + 2048 + 4096 + 256)
                     * (int)sizeof(float);
    cudaFuncSetAttribute(dp_kernel,
                         cudaFuncAttributeMaxDynamicSharedMemorySize, smem);

    max_kernel<<<dim3(LSEQ - 1, NB), 256>>>(scores);
    dp_kernel<<<dim3(2, NB), 1024, smem>>>(lens, out);
}

// round 15
// speedup vs baseline: 1.1452x; 1.1452x over previous
#include <cuda_runtime.h>
#include <cstddef>

#define LSEQ 256
#define NB   8
#define NC   64
#define PTOT 37120   // padded row-layout size (rs(255) = 36607)
#define DPAD 512     // slack for discarded-lane bulk reads

// t = max_c scores, padded-row layout: g_td[b*PTOT + rs(i) + (e-i-1)]
__device__ float g_td[NB * PTOT];

// Bank-aligned row starts, closed form: rs(i) % 32 == i % 32.
__host__ __device__ __forceinline__ int rs_pad(int i) {
    const int q = i >> 5, k = i & 31;
    const int g = (k <= 30) ? ((k * (k + 3)) >> 1) : 495;
    return i * 255 - ((i * (i - 1)) >> 1) + 496 * q + g;
}

// ---------------------------------------------------------------------------
// Kernel 1: t[b,i,e] = max over C of scores[b,i,e,:], upper triangle only.
// ---------------------------------------------------------------------------
__global__ void max_kernel(const float* __restrict__ scores) {
    const int i    = blockIdx.x;          // 0 .. 254
    const int b    = blockIdx.y;
    const int warp = threadIdx.x >> 5;
    const int lane = threadIdx.x & 31;
    const int base = b * PTOT + rs_pad(i) - i - 1;

    for (int e = i + 1 + warp; e < LSEQ; e += 8) {
        const float* p = scores + (((size_t)b * LSEQ + i) * LSEQ + e) * NC;
        float v = fmaxf(p[lane], p[lane + 32]);
        #pragma unroll
        for (int o = 16; o > 0; o >>= 1)
            v = fmaxf(v, __shfl_xor_sync(0xffffffffu, v, o));
        if (lane == 0)
            g_td[base + e] = v;
    }
}

// ---------------------------------------------------------------------------
// Kernel 2: CKY inside (max semiring), one 1024-thread CTA per batch,
// 4 widths per pass, SOFTWARE-PIPELINED: pass P's serial tail runs
// concurrently with pass P+1's bulk (which only touches diagonals <= w-5).
//
// Per pass P (base width w, widths w..w+3):
//  Phase 1 (concurrent):
//    warps 8-31 (768 thr): bulk-old(P): j in [8, w-5] (children <= w-5, all
//      complete before tail(P-1) started). Adaptive split: 768>>s groups.
//    warps 0-7 (256 thr): tail(P-1): per width, ordered terms only —
//      j in [1,d] (right diag fresh) and j in [w', wd-1] (left diag fresh) —
//      merged with VV(P-1), + t, store D. Partial barriers between substeps.
//      Then prefetch t for pass P's widths.
//  Phase 2 (all 1024): VV(P) = reduce group partials + old-safe boundary
//    terms j in [d+1,7] and [max(8, w-4), w-1] (diags <= w-1 done post-sync).
// Coverage: [1,d] + [d+1,7] + [8,w-5] + [max(8,w-4),w-1] + [w,wd-1]
//           = [1, wd-1]  (duplicates harmless: max is idempotent).
// ---------------------------------------------------------------------------
__global__ __launch_bounds__(1024, 1)
void dp_kernel(const int* __restrict__ lens, float* __restrict__ out) {
    const int b = blockIdx.x;
    extern __shared__ float S[];
    float* D  = S;                          // PTOT + DPAD chart
    float* P0 = S + PTOT + DPAD;            // 4 x 768 bulk partials
    float* VV = P0 + 4 * 768;               // 4 x 256 pre-combined
    int*   rs = (int*)(VV + 1024);          // padded row starts
    const float* tb  = g_td + b * PTOT;
    const int    tid = threadIdx.x;

    if (tid < 256) rs[tid] = rs_pad(tid);
    __syncthreads();
    if (tid < 255) D[rs[tid]] = tb[rs[tid]];        // width-1 diagonal
    __syncthreads();

    // Tail-thread state
    int   rsc = 0, lim = 0;
    float tt0 = 0.f, tt1 = 0.f, tt2 = 0.f, tt3 = 0.f;
    if (tid < 256) {
        rsc = rs[tid];
        lim = rsc + (tid < 254 ? 254 - tid : 0);  // last valid col of row tid
    }

    int wprev = 0;
    for (int w = 2; w < LSEQ; w += 4) {
        const int n = LSEQ - w;
        const int s = (n > 128) ? 8 : (n > 64) ? 7 : (n > 32) ? 6 : 5;

        // ================= Phase 1 (concurrent) =================
        if (tid >= 256) {
            // ---- bulk-old(P): j in [8, w-5], groups of 768>>s
            const int t7 = tid - 256;
            const int c  = t7 & ((1 << s) - 1);
            const int g  = t7 >> s;
            const int kk = 8 - s;                 // G = 3 << kk
            float a0 = -1e30f, a1 = -1e30f, a2 = -1e30f, a3 = -1e30f;
            const int m = w - 12;                 // count of [8, w-5]
            if (c < n && m > 0) {
                const int jlo = 8 + ((( g      * m) / 3) >> kk);
                const int jhi = 8 + (((( g + 1) * m) / 3) >> kk);
                if (jlo < jhi) {
                    const int lb = rs[c] - 1;     // left: D[lb + j]
                    int tp = c + jlo;
                    int rb = w - jlo - 1;
                    #pragma unroll 4
                    for (int j = jlo; j < jhi; ++j) {
                        const float L  = D[lb + j];
                        const int   ra = rs[tp] + rb;
                        a0 = fmaxf(a0, L + D[ra]);
                        a1 = fmaxf(a1, L + D[ra + 1]);
                        a2 = fmaxf(a2, L + D[ra + 2]);
                        a3 = fmaxf(a3, L + D[ra + 3]);
                        ++tp; --rb;
                    }
                }
            }
            P0[t7]        = a0;
            P0[768  + t7] = a1;
            P0[1536 + t7] = a2;
            P0[2304 + t7] = a3;
        } else {
            // ---- tail(P-1): ordered terms + store (skipped on first pass)
            if (w > 2) {
                #pragma unroll
                for (int d = 0; d < 4; ++d) {
                    const int wd = wprev + d;     // wprev <= w-4 <= 250
                    if (tid < LSEQ - wd) {
                        float v = VV[(d << 8) + tid];
                        #pragma unroll
                        for (int j = 1; j <= 3; ++j)      // j in [1, d]
                            if (j <= d)
                                v = fmaxf(v, D[rsc + j - 1] +
                                             D[rs[tid + j] + wd - j - 1]);
                        #pragma unroll
                        for (int e = 0; e < 3; ++e)       // j in [wprev, wd-1]
                            if (e < d)
                                v = fmaxf(v, D[rsc + wprev + e - 1] +
                                             D[rs[tid + wprev + e] + d - e - 1]);
                        const float tv = (d == 0) ? tt0 : (d == 1) ? tt1
                                       : (d == 2) ? tt2 : tt3;
                        D[rsc + wd - 1] = v + tv;
                    }
                    asm volatile("bar.sync 1, 256;" ::: "memory");
                }
            }
            // prefetch t for pass P's widths w..w+3 (consumed next pass)
            const int i0 = rsc + w - 1;
            tt0 = tb[i0     < lim ? i0     : lim];
            tt1 = tb[i0 + 1 < lim ? i0 + 1 : lim];
            tt2 = tb[i0 + 2 < lim ? i0 + 2 : lim];
            tt3 = tb[i0 + 3 < lim ? i0 + 3 : lim];
        }
        __syncthreads();

        // ================= Phase 2: pre-combine (all 1024) =================
        {
            const int d  = tid >> 8;
            const int cc = tid & 255;
            const int wd = w + d;
            float v = -1e30f;
            if (wd <= 255 && cc < LSEQ - wd) {
                const int G = 768 >> s;
                const float* PP = P0 + d * 768;
                for (int g = 0; g < G; ++g)
                    v = fmaxf(v, PP[(g << s) + cc]);
                const int rcb = rs[cc];
                // old-safe low terms: j in [d+1, min(7, w-1)]
                #pragma unroll
                for (int j = 1; j <= 7; ++j)
                    if (j > d && j < w)
                        v = fmaxf(v, D[rcb + j - 1] +
                                     D[rs[cc + j] + wd - j - 1]);
                // old-safe high terms: j in [max(8, w-4), w-1]
                const int j2 = (w - 4 > 8) ? w - 4 : 8;
                #pragma unroll
                for (int e = 0; e < 4; ++e) {
                    const int j = j2 + e;
                    if (j < w)
                        v = fmaxf(v, D[rcb + j - 1] +
                                     D[rs[cc + j] + wd - j - 1]);
                }
            }
            VV[tid] = v;                          // tid == (d<<8)+cc
        }
        __syncthreads();
        wprev = w;
    }

    // ---- final tail: wprev = 254 (widths 254, 255)
    if (tid < 256) {
        #pragma unroll
        for (int d = 0; d < 2; ++d) {
            const int wd = 254 + d;
            if (tid < LSEQ - wd) {
                float v = VV[(d << 8) + tid];
                if (d == 1)                        // j = 1
                    v = fmaxf(v, D[rsc] + D[rs[tid + 1] + wd - 2]);
                if (d == 1)                        // j = 254 (left fresh)
                    v = fmaxf(v, D[rsc + 253] + D[rs[tid + 254]]);
                const float tv = (d == 0) ? tt0 : tt1;
                D[rsc + wd - 1] = v + tv;
            }
            asm volatile("bar.sync 1, 256;" ::: "memory");
        }
    }
    __syncthreads();

    if (tid == 0) {
        int len = lens[b];
        len = len < 1 ? 1 : (len > 255 ? 255 : len);
        out[b] = D[len - 1];                 // s[0, len] = row 0, col len-1
    }
}

// ---------------------------------------------------------------------------
extern "C" void kernel_launch(void* const* d_in, const int* in_sizes, int n_in,
                              void* d_out, int out_size) {
    const float* scores = (const float*)d_in[0];
    const int*   lens   = (const int*)d_in[1];
    float*       out    = (float*)d_out;
    (void)in_sizes; (void)n_in; (void)out_size;

    const int smem = (PTOT + DPAD + 4 * 768 + 1024 + 256) * (int)sizeof(float);
    cudaFuncSetAttribute(dp_kernel,
                         cudaFuncAttributeMaxDynamicSharedMemorySize, smem);

    max_kernel<<<dim3(LSEQ - 1, NB), 256>>>(scores);
    dp_kernel<<<NB, 1024, smem>>>(lens, out);
}